// round 16
// baseline (speedup 1.0000x reference)
#include <cuda_runtime.h>

// NMS peak detection, exact — SINGLE persistent kernel with software grid barriers.
//   x: (8, 1, 1024, 1024) fp32
//   peak(p) <=> x[p] > 0.5 && no q in 51x51 window with x[q] > x[p]
//   output (float32): (4096, 4) rows [n, c, h, w] in row-major linear-index order, -1 fill.
//
// Phase 1 (cand):  warp == horizontal 16x16-tile pair (32x16 px), stride loop.
// Phase 2 (verify):warp == tile, stride loop. <=25 covering tiles probed via fixed 5x5
//                  map; fully-inside offender kills with zero element loads; boundary
//                  offenders get one parallel 8-load round (single ballot).
// Phase 3 (rank):  first 4096 peaks staged to SMEM (global fallback beyond);
//                  warp per peak, O(n^2/32) -> nonzero() order.
//
// Grid barrier: sense-reversing epoch barrier. NBLK=768 with __launch_bounds__(256,6)
// (regs<=42, smem ~16.2KB) -> 6 blocks/SM co-resident = 888 >= 768: no deadlock.
// Barrier count returns to 0 and the epoch only grows -> safe across graph replays.

#define IMG_SH 10          // 1024
#define NIMG   8
#define RAD    25
#define NT     64          // tiles per side
#define NTILES (NIMG * NT * NT)      // 32768
#define NPAIRS (NTILES / 2)          // 16384
#define MAXD   4096
#define PEAK_CAP 8192
#define SP_CAP 4096
#define FULL   0xffffffffu
#define NBLK   768
#define TOTW   (NBLK * 8)            // 6144 warps

__device__ int   g_cand[NTILES * 3];   // linear indices, -1 = empty
__device__ float g_tilemax[NTILES];
__device__ int   g_peak_count;
__device__ int   g_peaks[PEAK_CAP];
__device__ int   g_bar_count;          // zero-init; returns to zero after each barrier
__device__ int   g_bar_epoch;          // monotonically increasing

__device__ __forceinline__ void grid_barrier() {
    __syncthreads();
    if (threadIdx.x == 0) {
        __threadfence();
        const int old = atomicAdd(&g_bar_epoch, 0);   // read BEFORE arriving: safe
        if (atomicAdd(&g_bar_count, 1) == NBLK - 1) {
            atomicExch(&g_bar_count, 0);              // reset happens-before epoch bump
            __threadfence();
            atomicAdd(&g_bar_epoch, 1);
        } else {
            while (atomicAdd(&g_bar_epoch, 0) == old) { __nanosleep(64); }
        }
    }
    __syncthreads();
}

__global__ __launch_bounds__(256, 6)
void nms_kernel(const float* __restrict__ x, float* __restrict__ out) {
    __shared__ int scnt[16];
    __shared__ int sp[SP_CAP];

    const int tid  = threadIdx.x;
    const int lane = tid & 31;
    const int wid  = tid >> 5;
    const int bwarp = (blockIdx.x << 3) + wid;   // 0..TOTW-1

    // ── Phase 0 (fused): output -1 fill + peak counter reset ──
    if (blockIdx.x < 16)
        reinterpret_cast<float4*>(out)[(blockIdx.x << 8) + tid] =
            make_float4(-1.0f, -1.0f, -1.0f, -1.0f);
    if (blockIdx.x == 16 && tid == 0) g_peak_count = 0;

    // ── Phase 1: candidates ── stride loop over tile pairs.
    for (int tp = bwarp; tp < NPAIRS; tp += TOTW) {
        const int tileA = tp << 1;
        const int n     = tileA >> 12;
        const int ty    = (tileA >> 6) & 63;
        const int txA   = tileA & 63;                // even
        const int row0  = lane >> 3;                 // 0..3
        const int colp  = (lane & 7) << 2;           // 0..28 within 32-wide pair

        const float* base = x + ((size_t)n << 20)
                              + (((ty << 4) + row0) << IMG_SH)
                              + (txA << 4) + colp;

        const float4 f0 = *reinterpret_cast<const float4*>(base);
        const float4 f1 = *reinterpret_cast<const float4*>(base + (4 << IMG_SH));
        const float4 f2 = *reinterpret_cast<const float4*>(base + (8 << IMG_SH));
        const float4 f3 = *reinterpret_cast<const float4*>(base + (12 << IMG_SH));

        const float p = fmaxf(fmaxf(fmaxf(fmaxf(f0.x, f0.y), fmaxf(f0.z, f0.w)),
                                    fmaxf(fmaxf(f1.x, f1.y), fmaxf(f1.z, f1.w))),
                              fmaxf(fmaxf(fmaxf(f2.x, f2.y), fmaxf(f2.z, f2.w)),
                                    fmaxf(fmaxf(f3.x, f3.y), fmaxf(f3.z, f3.w))));

        float m = p;
        m = fmaxf(m, __shfl_xor_sync(FULL, m, 16));
        m = fmaxf(m, __shfl_xor_sync(FULL, m, 8));
        m = fmaxf(m, __shfl_xor_sync(FULL, m, 2));
        m = fmaxf(m, __shfl_xor_sync(FULL, m, 1));

        const int myTile = tileA + ((lane >> 2) & 1);
        if (lane == 0 || lane == 4) g_tilemax[myTile] = m;
        if (lane < 3)               g_cand[tileA * 3 + lane] = -1;
        if (lane >= 4 && lane < 7)  g_cand[(tileA + 1) * 3 + (lane - 4)] = -1;

        if (lane == 0 || lane == 4) scnt[(wid << 1) | (lane >> 2)] = 0;
        __syncwarp();

        if (m > 0.5f && p == m) {
            const int sidx = (wid << 1) | ((lane >> 2) & 1);
            const int lin0 = (n << 20) + (((ty << 4) + row0) << IMG_SH) + (txA << 4) + colp;
            const float v[16] = {f0.x, f0.y, f0.z, f0.w, f1.x, f1.y, f1.z, f1.w,
                                 f2.x, f2.y, f2.z, f2.w, f3.x, f3.y, f3.z, f3.w};
            #pragma unroll
            for (int k = 0; k < 16; ++k) {
                if (v[k] == m) {
                    int s = atomicAdd(&scnt[sidx], 1);
                    if (s < 3)
                        g_cand[myTile * 3 + s] = lin0 + ((k >> 2) << (IMG_SH + 2)) + (k & 3);
                }
            }
        }
        __syncwarp();
    }

    grid_barrier();

    // ── Phase 2: verify ── stride loop over tiles.
    for (int tile = bwarp; tile < NTILES; tile += TOTW) {
        const float pv = __ldg(&g_tilemax[tile]);
        int slot = (lane < 3) ? __ldg(&g_cand[tile * 3 + lane]) : -1;
        const int c0 = __shfl_sync(FULL, slot, 0);
        if (c0 < 0) continue;                        // tile max <= 0.5
        const int c1 = __shfl_sync(FULL, slot, 1);
        const int c2 = __shfl_sync(FULL, slot, 2);
        const int n = tile >> 12;
        const float* img = x + ((size_t)n << 20);
        const float* tm  = g_tilemax + (n << 12);

        #pragma unroll
        for (int k = 0; k < 3; ++k) {
            const int lin = (k == 0) ? c0 : (k == 1) ? c1 : c2;
            if (lin < 0) break;
            const int rem = lin & ((1 << 20) - 1);
            const int h = rem >> IMG_SH;
            const int w = rem & 1023;

            const int hlo = max(h - RAD, 0), hhi = min(h + RAD, 1023);
            const int wlo = max(w - RAD, 0), whi = min(w + RAD, 1023);
            const int tylo = hlo >> 4, tyhi = hhi >> 4;
            const int txlo = wlo >> 4, txhi = whi >> 4;

            const int dy = lane / 5, dx = lane - dy * 5;   // const div
            const int tty = tylo + dy, ttx = txlo + dx;
            bool off = false, inside = false;
            if (lane < 25 && tty <= tyhi && ttx <= txhi) {
                off = __ldg(&tm[(tty << 6) + ttx]) > pv;
                inside = ((tty << 4) >= hlo) & ((tty << 4) + 15 <= hhi) &
                         ((ttx << 4) >= wlo) & ((ttx << 4) + 15 <= whi);
            }
            if (__any_sync(FULL, off && inside)) continue;   // instant kill

            unsigned bmask = __ballot_sync(FULL, off && !inside);
            bool bad = false;
            while (bmask && !bad) {
                const int b = __ffs(bmask) - 1;
                bmask &= bmask - 1;
                const int by = b / 5;
                const int oty = tylo + by, otx = txlo + (b - by * 5);
                const int rlo = max(hlo, oty << 4), rhi = min(hhi, (oty << 4) + 15);
                const int clo = max(wlo, otx << 4), chi = min(whi, (otx << 4) + 15);
                const int ncm1 = chi - clo;                  // 0..15
                const int tot  = (rhi - rlo + 1) << 4;       // padded 16-wide rows
                float vmax = -1.0f;
                #pragma unroll
                for (int kk = 0; kk < 8; ++kk) {
                    const int i = lane + (kk << 5);
                    if (i < tot && (i & 15) <= ncm1) {
                        const int r = rlo + (i >> 4);
                        const int c = clo + (i & 15);
                        vmax = fmaxf(vmax, __ldg(&img[(r << IMG_SH) + c]));
                    }
                }
                bad = __any_sync(FULL, vmax > pv);
            }
            if (!bad && lane == 0) {
                int s = atomicAdd(&g_peak_count, 1);
                if (s < PEAK_CAP) g_peaks[s] = lin;
            }
        }
    }

    grid_barrier();

    // ── Phase 3: rank ── first SP_CAP peaks staged to SMEM (global fallback beyond).
    const int cnt = min(g_peak_count, PEAK_CAP);
    const int lim = min(cnt, SP_CAP);
    for (int j = tid; j < lim; j += 256) sp[j] = g_peaks[j];
    __syncthreads();

    for (int i = bwarp; i < cnt; i += TOTW) {
        const int lin = (i < lim) ? sp[i] : __ldg(&g_peaks[i]);
        int r = 0;
        int j = lane;
        for (; j < lim; j += 32) r += (sp[j] < lin);
        for (; j < cnt; j += 32) r += (__ldg(&g_peaks[j]) < lin);
        #pragma unroll
        for (int off = 16; off; off >>= 1)
            r += __shfl_xor_sync(FULL, r, off);
        if (lane == 0 && r < MAXD) {
            const int rem = lin & ((1 << 20) - 1);
            reinterpret_cast<float4*>(out)[r] =
                make_float4((float)(lin >> 20), 0.0f,
                            (float)(rem >> IMG_SH), (float)(rem & 1023));
        }
    }
}

extern "C" void kernel_launch(void* const* d_in, const int* in_sizes, int n_in,
                              void* d_out, int out_size) {
    const float* x = (const float*)d_in[0];
    float* out = (float*)d_out;

    nms_kernel<<<NBLK, 256>>>(x, out);
}